// round 5
// baseline (speedup 1.0000x reference)
#include <cuda_runtime.h>
#include <cuda_bf16.h>
#include <math.h>
#include <stdint.h>

// Problem dims
#define SEQ   128
#define BATCH 256
#define IND   1024
#define HID   1024
#define OUTD  1024
#define G4    4096
#define BH    (BATCH*HID)
#define KP    3072            // split-bf16 K' = 3*1024
#define BK    32
#define NC    (KP/BK)         // 96 k-chunks

// ---------------- scratch (device globals) ---------------------------------
__device__ float g_Xp[(size_t)SEQ * BATCH * G4];     // 512 MB (gate-interleaved cols)
__device__ float g_hs[(size_t)SEQ * BATCH * HID];    // 128 MB
__device__ float g_c[BATCH * HID];
__device__ float g_A[SEQ * SEQ];
__device__ float g_bias[G4];                          // gate-interleaved
__device__ __nv_bfloat16 g_Xbf[(size_t)SEQ * BATCH * KP];   // X' then att'
__device__ __nv_bfloat16 g_Wihp[(size_t)G4 * KP];           // gate-interleaved rows
__device__ __nv_bfloat16 g_Whhp[(size_t)G4 * KP];           // gate-interleaved rows
__device__ __nv_bfloat16 g_linWp[(size_t)OUTD * KP];
__device__ __nv_bfloat16 g_hp[(size_t)2 * BATCH * KP];      // double-buffered h'

// ---------------- PTX helpers ----------------------------------------------
__device__ __forceinline__ uint32_t smem_u32(const void* p) {
    uint32_t a;
    asm("{ .reg .u64 t; cvta.to.shared.u64 t, %1; cvt.u32.u64 %0, t; }"
        : "=r"(a) : "l"(p));
    return a;
}

#define CP_ASYNC16(dst, src) \
    asm volatile("cp.async.cg.shared.global [%0], [%1], 16;" :: "r"(dst), "l"(src))
#define CP_COMMIT()  asm volatile("cp.async.commit_group;" ::: "memory")
#define CP_WAIT1()   asm volatile("cp.async.wait_group 1;" ::: "memory")
#define CP_WAIT0()   asm volatile("cp.async.wait_group 0;" ::: "memory")

#define LDMX4(r0, r1, r2, r3, addr) \
    asm volatile("ldmatrix.sync.aligned.m8n8.x4.shared.b16 {%0,%1,%2,%3}, [%4];" \
                 : "=r"(r0), "=r"(r1), "=r"(r2), "=r"(r3) : "r"(addr))

#define MMA16816(d, a, b) \
    asm volatile("mma.sync.aligned.m16n8k16.row.col.f32.bf16.bf16.f32 " \
                 "{%0,%1,%2,%3}, {%4,%5,%6,%7}, {%8,%9}, {%0,%1,%2,%3};" \
                 : "+f"((d)[0]), "+f"((d)[1]), "+f"((d)[2]), "+f"((d)[3]) \
                 : "r"((a)[0]), "r"((a)[1]), "r"((a)[2]), "r"((a)[3]), \
                   "r"((b)[0]), "r"((b)[1]))

// swizzled 16B-chunk byte offset within a tile (row has 4 chunks of 8 bf16)
__device__ __forceinline__ uint32_t swz(int row, int c) {
    return (uint32_t)((row * 4 + (c ^ ((row >> 1) & 3))) * 16);
}

__device__ __forceinline__ float sigmf(float x) {
    return 1.0f / (1.0f + __expf(-x));
}

// ---------------- split-bf16 HMMA GEMM --------------------------------------
// C[M,N] = A'[M,KP] @ B'[N,KP]^T (+D)(+bias), fp32 accum.
// 256 threads = 8 warps (WGM x WGN). BK=32, double-buffered cp.async.
// FUSE=true: LSTM-cell epilogue (gate-interleaved cols), D = Xp_t mandatory.
template<int BM, int BN, int WGM, int WGN, bool FUSE>
__global__ __launch_bounds__(256)
void gemm_mma(const __nv_bfloat16* __restrict__ A,
              const __nv_bfloat16* __restrict__ B,
              const float* __restrict__ D,
              const float* __restrict__ bias,
              float* __restrict__ C,
              int N, int hasD, int hasBias,
              float* __restrict__ cst,
              float* __restrict__ hs_t,
              __nv_bfloat16* __restrict__ hp_dst)
{
    constexpr int WM = BM / WGM;
    constexpr int WN = BN / WGN;
    constexpr int MA = WM / 16;
    constexpr int NA = WN / 8;
    constexpr int A_BYTES = BM * BK * 2;
    constexpr int B_BYTES = BN * BK * 2;
    constexpr int STAGE   = A_BYTES + B_BYTES;
    constexpr int BNP     = BN + 4;

    extern __shared__ __align__(128) char smem[];
    const uint32_t sb = smem_u32(smem);

    const int tid = threadIdx.x;
    const int wid = tid >> 5;
    const int lid = tid & 31;
    const int g   = lid >> 2;
    const int tg  = lid & 3;
    const int wm  = wid / WGN;
    const int wn  = wid % WGN;
    const int bm0 = blockIdx.y * BM;
    const int bn0 = blockIdx.x * BN;

    float acc[MA][NA][4];
    #pragma unroll
    for (int i = 0; i < MA; ++i)
        #pragma unroll
        for (int j = 0; j < NA; ++j)
            #pragma unroll
            for (int q = 0; q < 4; ++q) acc[i][j][q] = 0.f;

    auto load_tile = [&](int c, int s) {
        const uint32_t abase = sb + s * STAGE;
        const uint32_t bbase = abase + A_BYTES;
        const int k0 = c * BK;
        #pragma unroll
        for (int u = tid; u < BM * 4; u += 256) {
            int r = u >> 2, cc = u & 3;
            CP_ASYNC16(abase + swz(r, cc),
                       A + (size_t)(bm0 + r) * KP + k0 + cc * 8);
        }
        #pragma unroll
        for (int u = tid; u < BN * 4; u += 256) {
            int r = u >> 2, cc = u & 3;
            CP_ASYNC16(bbase + swz(r, cc),
                       B + (size_t)(bn0 + r) * KP + k0 + cc * 8);
        }
    };

    load_tile(0, 0);
    CP_COMMIT();

    for (int c = 0; c < NC; ++c) {
        const int s = c & 1;
        if (c + 1 < NC) {
            load_tile(c + 1, s ^ 1);
            CP_COMMIT();
            CP_WAIT1();
        } else {
            CP_WAIT0();
        }
        __syncthreads();

        const uint32_t abase = sb + s * STAGE;
        const uint32_t bbase = abase + A_BYTES;

        #pragma unroll
        for (int ks = 0; ks < 2; ++ks) {
            uint32_t afr[MA][4];
            #pragma unroll
            for (int ma = 0; ma < MA; ++ma) {
                int row = wm * WM + ma * 16 + (lid & 15);
                int cc  = 2 * ks + (lid >> 4);
                LDMX4(afr[ma][0], afr[ma][1], afr[ma][2], afr[ma][3],
                      abase + swz(row, cc));
            }
            uint32_t bfr[NA][2];
            #pragma unroll
            for (int np = 0; np < NA / 2; ++np) {
                int row = wn * WN + np * 16 + (lid & 15);
                int cc  = 2 * ks + (lid >> 4);
                uint32_t r0, r1, r2, r3;
                LDMX4(r0, r1, r2, r3, bbase + swz(row, cc));
                bfr[2 * np + 0][0] = r0; bfr[2 * np + 1][0] = r1;
                bfr[2 * np + 0][1] = r2; bfr[2 * np + 1][1] = r3;
            }
            #pragma unroll
            for (int ma = 0; ma < MA; ++ma)
                #pragma unroll
                for (int na = 0; na < NA; ++na)
                    MMA16816(acc[ma][na], afr[ma], bfr[na]);
        }
        __syncthreads();
    }

    if constexpr (FUSE) {
        // ---- fused LSTM epilogue: acc -> smem -> quad-wise pointwise ----
        float* st = reinterpret_cast<float*>(smem);
        #pragma unroll
        for (int ma = 0; ma < MA; ++ma) {
            #pragma unroll
            for (int na = 0; na < NA; ++na) {
                const int col = wn * WN + na * 8 + tg * 2;
                const int r0  = wm * WM + ma * 16 + g;
                const int r1  = r0 + 8;
                st[r0 * BNP + col]     = acc[ma][na][0];
                st[r0 * BNP + col + 1] = acc[ma][na][1];
                st[r1 * BNP + col]     = acc[ma][na][2];
                st[r1 * BNP + col + 1] = acc[ma][na][3];
            }
        }
        __syncthreads();
        constexpr int QPB = BN / 4;   // quads per row
        for (int u = tid; u < BM * QPB; u += 256) {
            const int r  = u / QPB;
            const int jj = u % QPB;
            float4 gq = *reinterpret_cast<const float4*>(st + r * BNP + 4 * jj);
            const int b    = bm0 + r;
            const int col0 = bn0 + 4 * jj;
            float4 dq = *reinterpret_cast<const float4*>(D + (size_t)b * G4 + col0);
            float gi = sigmf(gq.x + dq.x);
            float gf = sigmf(gq.y + dq.y);
            float gg = tanhf(gq.z + dq.z);
            float go = sigmf(gq.w + dq.w);
            const int j    = col0 >> 2;
            const int cidx = b * HID + j;
            float cv = gf * cst[cidx] + gi * gg;
            cst[cidx] = cv;
            float h = go * tanhf(cv);
            hs_t[cidx] = h;
            __nv_bfloat16 hi = __float2bfloat16(h);
            float lo = h - __bfloat162float(hi);
            size_t hb = (size_t)b * KP + j;
            hp_dst[hb]        = hi;
            hp_dst[hb + 1024] = __float2bfloat16(lo);
            hp_dst[hb + 2048] = hi;
        }
    } else {
        #pragma unroll
        for (int ma = 0; ma < MA; ++ma) {
            #pragma unroll
            for (int na = 0; na < NA; ++na) {
                const int col = bn0 + wn * WN + na * 8 + tg * 2;
                const int r0  = bm0 + wm * WM + ma * 16 + g;
                const int r1  = r0 + 8;
                float2 v0 = make_float2(acc[ma][na][0], acc[ma][na][1]);
                float2 v1 = make_float2(acc[ma][na][2], acc[ma][na][3]);
                if (hasBias) {
                    float2 bv = *reinterpret_cast<const float2*>(bias + col);
                    v0.x += bv.x; v0.y += bv.y; v1.x += bv.x; v1.y += bv.y;
                }
                if (hasD) {
                    float2 d0 = *reinterpret_cast<const float2*>(D + (size_t)r0 * N + col);
                    float2 d1 = *reinterpret_cast<const float2*>(D + (size_t)r1 * N + col);
                    v0.x += d0.x; v0.y += d0.y; v1.x += d1.x; v1.y += d1.y;
                }
                *reinterpret_cast<float2*>(C + (size_t)r0 * N + col) = v0;
                *reinterpret_cast<float2*>(C + (size_t)r1 * N + col) = v1;
            }
        }
    }
}

// ---------------- conversion kernels ---------------------------------------
// A-side split: [hi | lo | hi] ; B-side split: [hi | hi | lo]
__global__ void conv_A(const float* __restrict__ W, __nv_bfloat16* __restrict__ Wp, int total)
{
    int i = blockIdx.x * blockDim.x + threadIdx.x;
    if (i >= total) return;
    int r = i >> 10, k = i & 1023;
    float w = W[i];
    __nv_bfloat16 hi = __float2bfloat16(w);
    float lo = w - __bfloat162float(hi);
    size_t base = (size_t)r * KP;
    Wp[base + k]        = hi;
    Wp[base + 1024 + k] = __float2bfloat16(lo);
    Wp[base + 2048 + k] = hi;
}

__global__ void conv_B(const float* __restrict__ W, __nv_bfloat16* __restrict__ Wp, int total)
{
    int i = blockIdx.x * blockDim.x + threadIdx.x;
    if (i >= total) return;
    int r = i >> 10, k = i & 1023;
    float w = W[i];
    __nv_bfloat16 hi = __float2bfloat16(w);
    float lo = w - __bfloat162float(hi);
    size_t base = (size_t)r * KP;
    Wp[base + k]        = hi;
    Wp[base + 1024 + k] = hi;
    Wp[base + 2048 + k] = __float2bfloat16(lo);
}

// gate-interleaved row permutation: orig row q*1024+j -> j*4+q
__global__ void conv_B_perm(const float* __restrict__ W, __nv_bfloat16* __restrict__ Wp, int total)
{
    int i = blockIdx.x * blockDim.x + threadIdx.x;
    if (i >= total) return;
    int r = i >> 10, k = i & 1023;
    int q = r >> 10, j = r & 1023;
    float w = W[i];
    __nv_bfloat16 hi = __float2bfloat16(w);
    float lo = w - __bfloat162float(hi);
    size_t base = (size_t)(j * 4 + q) * KP;
    Wp[base + k]        = hi;
    Wp[base + 1024 + k] = hi;
    Wp[base + 2048 + k] = __float2bfloat16(lo);
}

__global__ void init_c(const float* __restrict__ c0)
{
    int i = blockIdx.x * blockDim.x + threadIdx.x;
    if (i < BATCH * HID) g_c[i] = c0[i];
}

__global__ void bias_combine_perm(const float* __restrict__ b_ih, const float* __restrict__ b_hh)
{
    int i = blockIdx.x * blockDim.x + threadIdx.x;   // over G4
    if (i >= G4) return;
    int q = i >> 10, j = i & 1023;
    g_bias[j * 4 + q] = b_ih[i] + b_hh[i];
}

__global__ void softmax128(const float* __restrict__ W)
{
    int row = blockIdx.x;
    int t = threadIdx.x;
    int lane = t & 31, warp = t >> 5;
    __shared__ float red[4];
    float v = W[row * SEQ + t];

    float m = v;
    #pragma unroll
    for (int o = 16; o > 0; o >>= 1) m = fmaxf(m, __shfl_xor_sync(0xffffffffu, m, o));
    if (lane == 0) red[warp] = m;
    __syncthreads();
    m = fmaxf(fmaxf(red[0], red[1]), fmaxf(red[2], red[3]));
    __syncthreads();

    float e = expf(v - m);
    float s = e;
    #pragma unroll
    for (int o = 16; o > 0; o >>= 1) s += __shfl_xor_sync(0xffffffffu, s, o);
    if (lane == 0) red[warp] = s;
    __syncthreads();
    s = red[0] + red[1] + red[2] + red[3];
    g_A[row * SEQ + t] = e / s;
}

// att' (split-bf16 A-layout) = softmax(attnW) @ hs, written directly to g_Xbf
__global__ __launch_bounds__(128)
void attn_apply_fused()
{
    __shared__ float Asub[32][SEQ + 1];
    const int tid = threadIdx.x;
    const int n = blockIdx.x * 128 + tid;     // over BH (b*1024 + h)
    const int x0 = blockIdx.y * 32;

    for (int i = tid; i < 32 * SEQ; i += 128) {
        int xx = i >> 7;
        int y = i & 127;
        Asub[xx][y] = g_A[(x0 + xx) * SEQ + y];
    }
    __syncthreads();

    float acc[32];
    #pragma unroll
    for (int xx = 0; xx < 32; ++xx) acc[xx] = 0.f;

    for (int y = 0; y < SEQ; ++y) {
        float v = g_hs[(size_t)y * BH + n];
        #pragma unroll
        for (int xx = 0; xx < 32; ++xx)
            acc[xx] = fmaf(Asub[xx][y], v, acc[xx]);
    }

    const int b = n >> 10;
    const int h = n & 1023;
    #pragma unroll
    for (int xx = 0; xx < 32; ++xx) {
        float a = acc[xx];
        __nv_bfloat16 hi = __float2bfloat16(a);
        float lo = a - __bfloat162float(hi);
        size_t base = (size_t)((x0 + xx) * BATCH + b) * KP + h;
        g_Xbf[base]        = hi;
        g_Xbf[base + 1024] = __float2bfloat16(lo);
        g_Xbf[base + 2048] = hi;
    }
}

// ---------------- launch ----------------------------------------------------
extern "C" void kernel_launch(void* const* d_in, const int* in_sizes, int n_in,
                              void* d_out, int out_size)
{
    const float* inputs = (const float*)d_in[0];
    const float* h0     = (const float*)d_in[1];
    const float* c0     = (const float*)d_in[2];
    const float* W_ih   = (const float*)d_in[3];
    const float* W_hh   = (const float*)d_in[4];
    const float* b_ih   = (const float*)d_in[5];
    const float* b_hh   = (const float*)d_in[6];
    const float* attnW  = (const float*)d_in[7];
    const float* linW   = (const float*)d_in[8];
    const float* linb   = (const float*)d_in[9];
    float* out = (float*)d_out;

    void* p;
    cudaGetSymbolAddress(&p, g_Xp);    float* Xp    = (float*)p;
    cudaGetSymbolAddress(&p, g_hs);    float* hsb   = (float*)p;
    cudaGetSymbolAddress(&p, g_c);     float* cptr  = (float*)p;
    cudaGetSymbolAddress(&p, g_bias);  float* biasc = (float*)p;
    cudaGetSymbolAddress(&p, g_Xbf);   __nv_bfloat16* Xbf   = (__nv_bfloat16*)p;
    cudaGetSymbolAddress(&p, g_Wihp);  __nv_bfloat16* Wihp  = (__nv_bfloat16*)p;
    cudaGetSymbolAddress(&p, g_Whhp);  __nv_bfloat16* Whhp  = (__nv_bfloat16*)p;
    cudaGetSymbolAddress(&p, g_linWp); __nv_bfloat16* linWp = (__nv_bfloat16*)p;
    cudaGetSymbolAddress(&p, g_hp);    __nv_bfloat16* hp    = (__nv_bfloat16*)p;

    // smem sizes
    const int SMEM_BIG  = 2 * ((128 + 256) * BK * 2);                 // 49152
    const int PIPE_REC  = 2 * ((64 + 128) * BK * 2);                  // 24576
    const int EPI_REC   = 64 * (128 + 4) * 4;                          // 33792
    const int SMEM_REC  = (PIPE_REC > EPI_REC) ? PIPE_REC : EPI_REC;   // 33792

    cudaFuncSetAttribute((const void*)gemm_mma<128, 256, 2, 4, false>,
                         cudaFuncAttributeMaxDynamicSharedMemorySize, SMEM_BIG);
    cudaFuncSetAttribute((const void*)gemm_mma<64, 128, 2, 4, true>,
                         cudaFuncAttributeMaxDynamicSharedMemorySize, SMEM_REC);

    // conversions + init
    conv_B_perm<<<(G4 * 1024) / 256, 256>>>(W_ih, Wihp, G4 * 1024);
    conv_B_perm<<<(G4 * 1024) / 256, 256>>>(W_hh, Whhp, G4 * 1024);
    conv_B<<<(OUTD * 1024) / 256, 256>>>(linW, linWp, OUTD * 1024);
    conv_A<<<(SEQ * BATCH * 1024) / 256, 256>>>(inputs, Xbf, SEQ * BATCH * 1024);
    conv_A<<<(BATCH * 1024) / 256, 256>>>(h0, hp, BATCH * 1024);
    init_c<<<(BATCH * HID + 255) / 256, 256>>>(c0);
    bias_combine_perm<<<(G4 + 255) / 256, 256>>>(b_ih, b_hh);
    softmax128<<<SEQ, SEQ>>>(attnW);

    // Xp = X @ W_ih'^T + bias'   (gate-interleaved columns)
    gemm_mma<128, 256, 2, 4, false>
        <<<dim3(G4 / 256, (SEQ * BATCH) / 128), 256, SMEM_BIG>>>(
        Xbf, Wihp, nullptr, biasc, Xp, G4, 0, 1, nullptr, nullptr, nullptr);

    // recurrence: one fused kernel per step (GEMM + LSTM cell + h-split)
    const size_t HPSTRIDE = (size_t)BATCH * KP;
    for (int t = 0; t < SEQ; ++t) {
        gemm_mma<64, 128, 2, 4, true>
            <<<dim3(G4 / 128, BATCH / 64), 256, SMEM_REC>>>(
            hp + (size_t)(t & 1) * HPSTRIDE, Whhp,
            Xp + (size_t)t * BATCH * G4, nullptr, nullptr, G4, 1, 0,
            cptr, hsb + (size_t)t * BH, hp + (size_t)((t + 1) & 1) * HPSTRIDE);
    }

    // attention mix, emitting split-bf16 att' directly into Xbf
    attn_apply_fused<<<dim3(BH / 128, SEQ / 32), 128>>>();

    // out = att @ linW^T + linb
    gemm_mma<128, 256, 2, 4, false>
        <<<dim3(OUTD / 256, (SEQ * BATCH) / 128), 256, SMEM_BIG>>>(
        Xbf, linWp, nullptr, linb, out, OUTD, 0, 1, nullptr, nullptr, nullptr);
}

// round 6
// speedup vs baseline: 1.5682x; 1.5682x over previous
#include <cuda_runtime.h>
#include <cuda_bf16.h>
#include <math.h>
#include <stdint.h>

// Problem dims
#define SEQ   128
#define BATCH 256
#define IND   1024
#define HID   1024
#define OUTD  1024
#define G4    4096
#define BH    (BATCH*HID)
#define KP    3072            // split-bf16 K' = 3*1024
#define BK    32
#define NC    (KP/BK)         // 96 k-chunks

// ---------------- scratch (device globals) ---------------------------------
__device__ float g_Xp[(size_t)SEQ * BATCH * G4];     // 512 MB (gate-interleaved cols)
__device__ float g_hs[(size_t)SEQ * BATCH * HID];    // 128 MB
__device__ float g_c[BATCH * HID];
__device__ float g_A[SEQ * SEQ];
__device__ float g_bias[G4];                          // gate-interleaved
__device__ __nv_bfloat16 g_Xbf[(size_t)SEQ * BATCH * KP];   // X' then att'
__device__ __nv_bfloat16 g_Wihp[(size_t)G4 * KP];           // gate-interleaved rows
__device__ __nv_bfloat16 g_Whhp[(size_t)G4 * KP];           // gate-interleaved rows
__device__ __nv_bfloat16 g_linWp[(size_t)OUTD * KP];
__device__ __nv_bfloat16 g_hp[(size_t)2 * BATCH * KP];      // double-buffered h'

// ---------------- PTX helpers ----------------------------------------------
__device__ __forceinline__ uint32_t smem_u32(const void* p) {
    uint32_t a;
    asm("{ .reg .u64 t; cvta.to.shared.u64 t, %1; cvt.u32.u64 %0, t; }"
        : "=r"(a) : "l"(p));
    return a;
}

#define CP_ASYNC16(dst, src) \
    asm volatile("cp.async.cg.shared.global [%0], [%1], 16;" :: "r"(dst), "l"(src))
#define CP_COMMIT()  asm volatile("cp.async.commit_group;" ::: "memory")
#define CP_WAIT1()   asm volatile("cp.async.wait_group 1;" ::: "memory")
#define CP_WAIT0()   asm volatile("cp.async.wait_group 0;" ::: "memory")

#define LDMX4(r0, r1, r2, r3, addr) \
    asm volatile("ldmatrix.sync.aligned.m8n8.x4.shared.b16 {%0,%1,%2,%3}, [%4];" \
                 : "=r"(r0), "=r"(r1), "=r"(r2), "=r"(r3) : "r"(addr))

#define MMA16816(d, a, b) \
    asm volatile("mma.sync.aligned.m16n8k16.row.col.f32.bf16.bf16.f32 " \
                 "{%0,%1,%2,%3}, {%4,%5,%6,%7}, {%8,%9}, {%0,%1,%2,%3};" \
                 : "+f"((d)[0]), "+f"((d)[1]), "+f"((d)[2]), "+f"((d)[3]) \
                 : "r"((a)[0]), "r"((a)[1]), "r"((a)[2]), "r"((a)[3]), \
                   "r"((b)[0]), "r"((b)[1]))

// swizzled 16B-chunk byte offset within a tile (row has 4 chunks of 8 bf16)
__device__ __forceinline__ uint32_t swz(int row, int c) {
    return (uint32_t)((row * 4 + (c ^ ((row >> 1) & 3))) * 16);
}

__device__ __forceinline__ float sigmf(float x) {
    return 1.0f / (1.0f + __expf(-x));
}

// ---------------- split-bf16 HMMA GEMM --------------------------------------
// C[M,N] = A'[M,KP] @ B'[N,KP]^T (+D)(+bias), fp32 accum.
// 256 threads = 8 warps (WGM x WGN). BK=32, double-buffered cp.async.
// FUSE=true: LSTM-cell epilogue (gate-interleaved cols), D = Xp_t mandatory.
template<int BM, int BN, int WGM, int WGN, bool FUSE>
__global__ __launch_bounds__(256)
void gemm_mma(const __nv_bfloat16* __restrict__ A,
              const __nv_bfloat16* __restrict__ B,
              const float* __restrict__ D,
              const float* __restrict__ bias,
              float* __restrict__ C,
              int N, int hasD, int hasBias,
              float* __restrict__ cst,
              float* __restrict__ hs_t,
              __nv_bfloat16* __restrict__ hp_dst)
{
    constexpr int WM = BM / WGM;
    constexpr int WN = BN / WGN;
    constexpr int MA = WM / 16;
    constexpr int NA = WN / 8;
    constexpr int A_BYTES = BM * BK * 2;
    constexpr int B_BYTES = BN * BK * 2;
    constexpr int STAGE   = A_BYTES + B_BYTES;
    constexpr int BNP     = BN + 4;

    extern __shared__ __align__(128) char smem[];
    const uint32_t sb = smem_u32(smem);

    const int tid = threadIdx.x;
    const int wid = tid >> 5;
    const int lid = tid & 31;
    const int g   = lid >> 2;
    const int tg  = lid & 3;
    const int wm  = wid / WGN;
    const int wn  = wid % WGN;
    const int bm0 = blockIdx.y * BM;
    const int bn0 = blockIdx.x * BN;

    float acc[MA][NA][4];
    #pragma unroll
    for (int i = 0; i < MA; ++i)
        #pragma unroll
        for (int j = 0; j < NA; ++j)
            #pragma unroll
            for (int q = 0; q < 4; ++q) acc[i][j][q] = 0.f;

    auto load_tile = [&](int c, int s) {
        const uint32_t abase = sb + s * STAGE;
        const uint32_t bbase = abase + A_BYTES;
        const int k0 = c * BK;
        #pragma unroll
        for (int u = tid; u < BM * 4; u += 256) {
            int r = u >> 2, cc = u & 3;
            CP_ASYNC16(abase + swz(r, cc),
                       A + (size_t)(bm0 + r) * KP + k0 + cc * 8);
        }
        #pragma unroll
        for (int u = tid; u < BN * 4; u += 256) {
            int r = u >> 2, cc = u & 3;
            CP_ASYNC16(bbase + swz(r, cc),
                       B + (size_t)(bn0 + r) * KP + k0 + cc * 8);
        }
    };

    load_tile(0, 0);
    CP_COMMIT();

    for (int c = 0; c < NC; ++c) {
        const int s = c & 1;
        if (c + 1 < NC) {
            load_tile(c + 1, s ^ 1);
            CP_COMMIT();
            CP_WAIT1();
        } else {
            CP_WAIT0();
        }
        __syncthreads();

        const uint32_t abase = sb + s * STAGE;
        const uint32_t bbase = abase + A_BYTES;

        #pragma unroll
        for (int ks = 0; ks < 2; ++ks) {
            uint32_t afr[MA][4];
            #pragma unroll
            for (int ma = 0; ma < MA; ++ma) {
                int row = wm * WM + ma * 16 + (lid & 15);
                int cc  = 2 * ks + (lid >> 4);
                LDMX4(afr[ma][0], afr[ma][1], afr[ma][2], afr[ma][3],
                      abase + swz(row, cc));
            }
            uint32_t bfr[NA][2];
            #pragma unroll
            for (int np = 0; np < NA / 2; ++np) {
                int row = wn * WN + np * 16 + (lid & 15);
                int cc  = 2 * ks + (lid >> 4);
                uint32_t r0, r1, r2, r3;
                LDMX4(r0, r1, r2, r3, bbase + swz(row, cc));
                bfr[2 * np + 0][0] = r0; bfr[2 * np + 1][0] = r1;
                bfr[2 * np + 0][1] = r2; bfr[2 * np + 1][1] = r3;
            }
            #pragma unroll
            for (int ma = 0; ma < MA; ++ma)
                #pragma unroll
                for (int na = 0; na < NA; ++na)
                    MMA16816(acc[ma][na], afr[ma], bfr[na]);
        }
        __syncthreads();
    }

    if constexpr (FUSE) {
        // ---- fused LSTM epilogue: acc -> smem -> quad-wise pointwise ----
        float* st = reinterpret_cast<float*>(smem);
        #pragma unroll
        for (int ma = 0; ma < MA; ++ma) {
            #pragma unroll
            for (int na = 0; na < NA; ++na) {
                const int col = wn * WN + na * 8 + tg * 2;
                const int r0  = wm * WM + ma * 16 + g;
                const int r1  = r0 + 8;
                st[r0 * BNP + col]     = acc[ma][na][0];
                st[r0 * BNP + col + 1] = acc[ma][na][1];
                st[r1 * BNP + col]     = acc[ma][na][2];
                st[r1 * BNP + col + 1] = acc[ma][na][3];
            }
        }
        __syncthreads();
        constexpr int QPB = BN / 4;   // quads per row
        for (int u = tid; u < BM * QPB; u += 256) {
            const int r  = u / QPB;
            const int jj = u % QPB;
            float4 gq = *reinterpret_cast<const float4*>(st + r * BNP + 4 * jj);
            const int b    = bm0 + r;
            const int col0 = bn0 + 4 * jj;
            float4 dq = *reinterpret_cast<const float4*>(D + (size_t)b * G4 + col0);
            float gi = sigmf(gq.x + dq.x);
            float gf = sigmf(gq.y + dq.y);
            float gg = tanhf(gq.z + dq.z);
            float go = sigmf(gq.w + dq.w);
            const int j    = col0 >> 2;
            const int cidx = b * HID + j;
            float cv = gf * cst[cidx] + gi * gg;
            cst[cidx] = cv;
            float h = go * tanhf(cv);
            hs_t[cidx] = h;
            __nv_bfloat16 hi = __float2bfloat16(h);
            float lo = h - __bfloat162float(hi);
            size_t hb = (size_t)b * KP + j;
            hp_dst[hb]        = hi;
            hp_dst[hb + 1024] = __float2bfloat16(lo);
            hp_dst[hb + 2048] = hi;
        }
    } else {
        #pragma unroll
        for (int ma = 0; ma < MA; ++ma) {
            #pragma unroll
            for (int na = 0; na < NA; ++na) {
                const int col = bn0 + wn * WN + na * 8 + tg * 2;
                const int r0  = bm0 + wm * WM + ma * 16 + g;
                const int r1  = r0 + 8;
                float2 v0 = make_float2(acc[ma][na][0], acc[ma][na][1]);
                float2 v1 = make_float2(acc[ma][na][2], acc[ma][na][3]);
                if (hasBias) {
                    float2 bv = *reinterpret_cast<const float2*>(bias + col);
                    v0.x += bv.x; v0.y += bv.y; v1.x += bv.x; v1.y += bv.y;
                }
                if (hasD) {
                    float2 d0 = *reinterpret_cast<const float2*>(D + (size_t)r0 * N + col);
                    float2 d1 = *reinterpret_cast<const float2*>(D + (size_t)r1 * N + col);
                    v0.x += d0.x; v0.y += d0.y; v1.x += d1.x; v1.y += d1.y;
                }
                *reinterpret_cast<float2*>(C + (size_t)r0 * N + col) = v0;
                *reinterpret_cast<float2*>(C + (size_t)r1 * N + col) = v1;
            }
        }
    }
}

// ---------------- conversion kernels ---------------------------------------
// A-side split: [hi | lo | hi] ; B-side split: [hi | hi | lo]
__global__ void conv_A(const float* __restrict__ W, __nv_bfloat16* __restrict__ Wp, int total)
{
    int i = blockIdx.x * blockDim.x + threadIdx.x;
    if (i >= total) return;
    int r = i >> 10, k = i & 1023;
    float w = W[i];
    __nv_bfloat16 hi = __float2bfloat16(w);
    float lo = w - __bfloat162float(hi);
    size_t base = (size_t)r * KP;
    Wp[base + k]        = hi;
    Wp[base + 1024 + k] = __float2bfloat16(lo);
    Wp[base + 2048 + k] = hi;
}

__global__ void conv_B(const float* __restrict__ W, __nv_bfloat16* __restrict__ Wp, int total)
{
    int i = blockIdx.x * blockDim.x + threadIdx.x;
    if (i >= total) return;
    int r = i >> 10, k = i & 1023;
    float w = W[i];
    __nv_bfloat16 hi = __float2bfloat16(w);
    float lo = w - __bfloat162float(hi);
    size_t base = (size_t)r * KP;
    Wp[base + k]        = hi;
    Wp[base + 1024 + k] = hi;
    Wp[base + 2048 + k] = __float2bfloat16(lo);
}

// gate-interleaved row permutation: orig row q*1024+j -> j*4+q
__global__ void conv_B_perm(const float* __restrict__ W, __nv_bfloat16* __restrict__ Wp, int total)
{
    int i = blockIdx.x * blockDim.x + threadIdx.x;
    if (i >= total) return;
    int r = i >> 10, k = i & 1023;
    int q = r >> 10, j = r & 1023;
    float w = W[i];
    __nv_bfloat16 hi = __float2bfloat16(w);
    float lo = w - __bfloat162float(hi);
    size_t base = (size_t)(j * 4 + q) * KP;
    Wp[base + k]        = hi;
    Wp[base + 1024 + k] = hi;
    Wp[base + 2048 + k] = __float2bfloat16(lo);
}

__global__ void init_c(const float* __restrict__ c0)
{
    int i = blockIdx.x * blockDim.x + threadIdx.x;
    if (i < BATCH * HID) g_c[i] = c0[i];
}

__global__ void bias_combine_perm(const float* __restrict__ b_ih, const float* __restrict__ b_hh)
{
    int i = blockIdx.x * blockDim.x + threadIdx.x;   // over G4
    if (i >= G4) return;
    int q = i >> 10, j = i & 1023;
    g_bias[j * 4 + q] = b_ih[i] + b_hh[i];
}

__global__ void softmax128(const float* __restrict__ W)
{
    int row = blockIdx.x;
    int t = threadIdx.x;
    int lane = t & 31, warp = t >> 5;
    __shared__ float red[4];
    float v = W[row * SEQ + t];

    float m = v;
    #pragma unroll
    for (int o = 16; o > 0; o >>= 1) m = fmaxf(m, __shfl_xor_sync(0xffffffffu, m, o));
    if (lane == 0) red[warp] = m;
    __syncthreads();
    m = fmaxf(fmaxf(red[0], red[1]), fmaxf(red[2], red[3]));
    __syncthreads();

    float e = expf(v - m);
    float s = e;
    #pragma unroll
    for (int o = 16; o > 0; o >>= 1) s += __shfl_xor_sync(0xffffffffu, s, o);
    if (lane == 0) red[warp] = s;
    __syncthreads();
    s = red[0] + red[1] + red[2] + red[3];
    g_A[row * SEQ + t] = e / s;
}

// att' (split-bf16 A-layout) = softmax(attnW) @ hs, written directly to g_Xbf
__global__ __launch_bounds__(128)
void attn_apply_fused()
{
    __shared__ float Asub[32][SEQ + 1];
    const int tid = threadIdx.x;
    const int n = blockIdx.x * 128 + tid;     // over BH (b*1024 + h)
    const int x0 = blockIdx.y * 32;

    for (int i = tid; i < 32 * SEQ; i += 128) {
        int xx = i >> 7;
        int y = i & 127;
        Asub[xx][y] = g_A[(x0 + xx) * SEQ + y];
    }
    __syncthreads();

    float acc[32];
    #pragma unroll
    for (int xx = 0; xx < 32; ++xx) acc[xx] = 0.f;

    for (int y = 0; y < SEQ; ++y) {
        float v = g_hs[(size_t)y * BH + n];
        #pragma unroll
        for (int xx = 0; xx < 32; ++xx)
            acc[xx] = fmaf(Asub[xx][y], v, acc[xx]);
    }

    const int b = n >> 10;
    const int h = n & 1023;
    #pragma unroll
    for (int xx = 0; xx < 32; ++xx) {
        float a = acc[xx];
        __nv_bfloat16 hi = __float2bfloat16(a);
        float lo = a - __bfloat162float(hi);
        size_t base = (size_t)((x0 + xx) * BATCH + b) * KP + h;
        g_Xbf[base]        = hi;
        g_Xbf[base + 1024] = __float2bfloat16(lo);
        g_Xbf[base + 2048] = hi;
    }
}

// ---------------- launch ----------------------------------------------------
extern "C" void kernel_launch(void* const* d_in, const int* in_sizes, int n_in,
                              void* d_out, int out_size)
{
    const float* inputs = (const float*)d_in[0];
    const float* h0     = (const float*)d_in[1];
    const float* c0     = (const float*)d_in[2];
    const float* W_ih   = (const float*)d_in[3];
    const float* W_hh   = (const float*)d_in[4];
    const float* b_ih   = (const float*)d_in[5];
    const float* b_hh   = (const float*)d_in[6];
    const float* attnW  = (const float*)d_in[7];
    const float* linW   = (const float*)d_in[8];
    const float* linb   = (const float*)d_in[9];
    float* out = (float*)d_out;

    void* p;
    cudaGetSymbolAddress(&p, g_Xp);    float* Xp    = (float*)p;
    cudaGetSymbolAddress(&p, g_hs);    float* hsb   = (float*)p;
    cudaGetSymbolAddress(&p, g_c);     float* cptr  = (float*)p;
    cudaGetSymbolAddress(&p, g_bias);  float* biasc = (float*)p;
    cudaGetSymbolAddress(&p, g_Xbf);   __nv_bfloat16* Xbf   = (__nv_bfloat16*)p;
    cudaGetSymbolAddress(&p, g_Wihp);  __nv_bfloat16* Wihp  = (__nv_bfloat16*)p;
    cudaGetSymbolAddress(&p, g_Whhp);  __nv_bfloat16* Whhp  = (__nv_bfloat16*)p;
    cudaGetSymbolAddress(&p, g_linWp); __nv_bfloat16* linWp = (__nv_bfloat16*)p;
    cudaGetSymbolAddress(&p, g_hp);    __nv_bfloat16* hp    = (__nv_bfloat16*)p;

    // smem sizes
    const int SMEM_BIG  = 2 * ((128 + 128) * BK * 2);                 // 32768 (128x128 tile)
    const int PIPE_REC  = 2 * ((64 + 128) * BK * 2);                  // 24576
    const int EPI_REC   = 64 * (128 + 4) * 4;                          // 33792
    const int SMEM_REC  = (PIPE_REC > EPI_REC) ? PIPE_REC : EPI_REC;   // 33792

    cudaFuncSetAttribute((const void*)gemm_mma<128, 128, 2, 4, false>,
                         cudaFuncAttributeMaxDynamicSharedMemorySize, SMEM_BIG);
    cudaFuncSetAttribute((const void*)gemm_mma<64, 128, 2, 4, true>,
                         cudaFuncAttributeMaxDynamicSharedMemorySize, SMEM_REC);

    // conversions + init
    conv_B_perm<<<(G4 * 1024) / 256, 256>>>(W_ih, Wihp, G4 * 1024);
    conv_B_perm<<<(G4 * 1024) / 256, 256>>>(W_hh, Whhp, G4 * 1024);
    conv_B<<<(OUTD * 1024) / 256, 256>>>(linW, linWp, OUTD * 1024);
    conv_A<<<(SEQ * BATCH * 1024) / 256, 256>>>(inputs, Xbf, SEQ * BATCH * 1024);
    conv_A<<<(BATCH * 1024) / 256, 256>>>(h0, hp, BATCH * 1024);
    init_c<<<(BATCH * HID + 255) / 256, 256>>>(c0);
    bias_combine_perm<<<(G4 + 255) / 256, 256>>>(b_ih, b_hh);
    softmax128<<<SEQ, SEQ>>>(attnW);

    // Xp = X @ W_ih'^T + bias'   (gate-interleaved columns)
    gemm_mma<128, 128, 2, 4, false>
        <<<dim3(G4 / 128, (SEQ * BATCH) / 128), 256, SMEM_BIG>>>(
        Xbf, Wihp, nullptr, biasc, Xp, G4, 0, 1, nullptr, nullptr, nullptr);

    // recurrence: one fused kernel per step (GEMM + LSTM cell + h-split)
    const size_t HPSTRIDE = (size_t)BATCH * KP;
    for (int t = 0; t < SEQ; ++t) {
        gemm_mma<64, 128, 2, 4, true>
            <<<dim3(G4 / 128, BATCH / 64), 256, SMEM_REC>>>(
            hp + (size_t)(t & 1) * HPSTRIDE, Whhp,
            Xp + (size_t)t * BATCH * G4, nullptr, nullptr, G4, 1, 0,
            cptr, hsb + (size_t)t * BH, hp + (size_t)((t + 1) & 1) * HPSTRIDE);
    }

    // attention mix, emitting split-bf16 att' directly into Xbf
    attn_apply_fused<<<dim3(BH / 128, SEQ / 32), 128>>>();

    // out = att @ linW^T + linb
    gemm_mma<128, 128, 2, 4, false>
        <<<dim3(OUTD / 128, (SEQ * BATCH) / 128), 256, SMEM_BIG>>>(
        Xbf, linWp, nullptr, linb, out, OUTD, 0, 1, nullptr, nullptr, nullptr);
}

// round 7
// speedup vs baseline: 1.6874x; 1.0760x over previous
#include <cuda_runtime.h>
#include <cuda_bf16.h>
#include <math.h>
#include <stdint.h>

// Problem dims
#define SEQ   128
#define BATCH 256
#define IND   1024
#define HID   1024
#define OUTD  1024
#define G4    4096
#define BH    (BATCH*HID)
#define KP    3072            // split-bf16 K' = 3*1024
#define BK    32
#define NC    (KP/BK)         // 96 k-chunks

// ---------------- scratch (device globals) ---------------------------------
__device__ float g_Xp[(size_t)SEQ * BATCH * G4];     // 512 MB (gate-interleaved cols)
__device__ float g_hs[(size_t)SEQ * BATCH * HID];    // 128 MB
__device__ float g_A[SEQ * SEQ];
__device__ float g_bias[G4];                          // gate-interleaved
__device__ __nv_bfloat16 g_Xbf[(size_t)SEQ * BATCH * KP];   // X' then att'
__device__ __nv_bfloat16 g_Wihp[(size_t)G4 * KP];           // gate-interleaved rows
__device__ __nv_bfloat16 g_Whhp[(size_t)G4 * KP];           // gate-interleaved rows
__device__ __nv_bfloat16 g_linWp[(size_t)OUTD * KP];
__device__ __nv_bfloat16 g_hp[(size_t)2 * BATCH * KP];      // double-buffered h'
__device__ unsigned g_bar_cnt;
__device__ unsigned g_bar_gen;

// ---------------- PTX helpers ----------------------------------------------
__device__ __forceinline__ uint32_t smem_u32(const void* p) {
    uint32_t a;
    asm("{ .reg .u64 t; cvta.to.shared.u64 t, %1; cvt.u32.u64 %0, t; }"
        : "=r"(a) : "l"(p));
    return a;
}

#define CP_ASYNC16(dst, src) \
    asm volatile("cp.async.cg.shared.global [%0], [%1], 16;" :: "r"(dst), "l"(src))
#define CP_COMMIT()  asm volatile("cp.async.commit_group;" ::: "memory")
#define CP_WAIT2()   asm volatile("cp.async.wait_group 2;" ::: "memory")
#define CP_WAIT1()   asm volatile("cp.async.wait_group 1;" ::: "memory")
#define CP_WAIT0()   asm volatile("cp.async.wait_group 0;" ::: "memory")

#define LDMX4(r0, r1, r2, r3, addr) \
    asm volatile("ldmatrix.sync.aligned.m8n8.x4.shared.b16 {%0,%1,%2,%3}, [%4];" \
                 : "=r"(r0), "=r"(r1), "=r"(r2), "=r"(r3) : "r"(addr))

#define MMA16816(d, a, b) \
    asm volatile("mma.sync.aligned.m16n8k16.row.col.f32.bf16.bf16.f32 " \
                 "{%0,%1,%2,%3}, {%4,%5,%6,%7}, {%8,%9}, {%0,%1,%2,%3};" \
                 : "+f"((d)[0]), "+f"((d)[1]), "+f"((d)[2]), "+f"((d)[3]) \
                 : "r"((a)[0]), "r"((a)[1]), "r"((a)[2]), "r"((a)[3]), \
                   "r"((b)[0]), "r"((b)[1]))

// swizzled 16B-chunk byte offset within a tile (row has 4 chunks of 8 bf16)
__device__ __forceinline__ uint32_t swz(int row, int c) {
    return (uint32_t)((row * 4 + (c ^ ((row >> 1) & 3))) * 16);
}

__device__ __forceinline__ float sigmf(float x) {
    return 1.0f / (1.0f + __expf(-x));
}

__device__ __forceinline__ unsigned ld_acq(unsigned* p) {
    unsigned v;
    asm volatile("ld.acquire.gpu.global.u32 %0, [%1];" : "=r"(v) : "l"(p) : "memory");
    return v;
}

// ---------------- split-bf16 HMMA GEMM (big GEMMs) --------------------------
// C[M,N] = A'[M,KP] @ B'[N,KP]^T (+bias), fp32 accum.
// 256 threads = 8 warps (WGM x WGN). BK=32, double-buffered cp.async.
template<int BM, int BN, int WGM, int WGN>
__global__ __launch_bounds__(256)
void gemm_mma(const __nv_bfloat16* __restrict__ A,
              const __nv_bfloat16* __restrict__ B,
              const float* __restrict__ bias,
              float* __restrict__ C,
              int N, int hasBias)
{
    constexpr int WM = BM / WGM;
    constexpr int WN = BN / WGN;
    constexpr int MA = WM / 16;
    constexpr int NA = WN / 8;
    constexpr int A_BYTES = BM * BK * 2;
    constexpr int B_BYTES = BN * BK * 2;
    constexpr int STAGE   = A_BYTES + B_BYTES;

    extern __shared__ __align__(128) char smem[];
    const uint32_t sb = smem_u32(smem);

    const int tid = threadIdx.x;
    const int wid = tid >> 5;
    const int lid = tid & 31;
    const int g   = lid >> 2;
    const int tg  = lid & 3;
    const int wm  = wid / WGN;
    const int wn  = wid % WGN;
    const int bm0 = blockIdx.y * BM;
    const int bn0 = blockIdx.x * BN;

    float acc[MA][NA][4];
    #pragma unroll
    for (int i = 0; i < MA; ++i)
        #pragma unroll
        for (int j = 0; j < NA; ++j)
            #pragma unroll
            for (int q = 0; q < 4; ++q) acc[i][j][q] = 0.f;

    auto load_tile = [&](int c, int s) {
        const uint32_t abase = sb + s * STAGE;
        const uint32_t bbase = abase + A_BYTES;
        const int k0 = c * BK;
        #pragma unroll
        for (int u = tid; u < BM * 4; u += 256) {
            int r = u >> 2, cc = u & 3;
            CP_ASYNC16(abase + swz(r, cc),
                       A + (size_t)(bm0 + r) * KP + k0 + cc * 8);
        }
        #pragma unroll
        for (int u = tid; u < BN * 4; u += 256) {
            int r = u >> 2, cc = u & 3;
            CP_ASYNC16(bbase + swz(r, cc),
                       B + (size_t)(bn0 + r) * KP + k0 + cc * 8);
        }
    };

    load_tile(0, 0);
    CP_COMMIT();

    for (int c = 0; c < NC; ++c) {
        const int s = c & 1;
        if (c + 1 < NC) {
            load_tile(c + 1, s ^ 1);
            CP_COMMIT();
            CP_WAIT1();
        } else {
            CP_WAIT0();
        }
        __syncthreads();

        const uint32_t abase = sb + s * STAGE;
        const uint32_t bbase = abase + A_BYTES;

        #pragma unroll
        for (int ks = 0; ks < 2; ++ks) {
            uint32_t afr[MA][4];
            #pragma unroll
            for (int ma = 0; ma < MA; ++ma) {
                int row = wm * WM + ma * 16 + (lid & 15);
                int cc  = 2 * ks + (lid >> 4);
                LDMX4(afr[ma][0], afr[ma][1], afr[ma][2], afr[ma][3],
                      abase + swz(row, cc));
            }
            uint32_t bfr[NA][2];
            #pragma unroll
            for (int np = 0; np < NA / 2; ++np) {
                int row = wn * WN + np * 16 + (lid & 15);
                int cc  = 2 * ks + (lid >> 4);
                uint32_t r0, r1, r2, r3;
                LDMX4(r0, r1, r2, r3, bbase + swz(row, cc));
                bfr[2 * np + 0][0] = r0; bfr[2 * np + 1][0] = r1;
                bfr[2 * np + 0][1] = r2; bfr[2 * np + 1][1] = r3;
            }
            #pragma unroll
            for (int ma = 0; ma < MA; ++ma)
                #pragma unroll
                for (int na = 0; na < NA; ++na)
                    MMA16816(acc[ma][na], afr[ma], bfr[na]);
        }
        __syncthreads();
    }

    #pragma unroll
    for (int ma = 0; ma < MA; ++ma) {
        #pragma unroll
        for (int na = 0; na < NA; ++na) {
            const int col = bn0 + wn * WN + na * 8 + tg * 2;
            const int r0  = bm0 + wm * WM + ma * 16 + g;
            const int r1  = r0 + 8;
            float2 v0 = make_float2(acc[ma][na][0], acc[ma][na][1]);
            float2 v1 = make_float2(acc[ma][na][2], acc[ma][na][3]);
            if (hasBias) {
                float2 bv = *reinterpret_cast<const float2*>(bias + col);
                v0.x += bv.x; v0.y += bv.y; v1.x += bv.x; v1.y += bv.y;
            }
            *reinterpret_cast<float2*>(C + (size_t)r0 * N + col) = v0;
            *reinterpret_cast<float2*>(C + (size_t)r1 * N + col) = v1;
        }
    }
}

// ---------------- persistent LSTM recurrence --------------------------------
// 128 CTAs (grid 32x4), all resident. Per step: 64x128 tile of
// gates = h' @ W_hh'^T (K'=3072, BK=32, 4-stage cp.async pipeline),
// Xp[t] tile prefetched to smem with chunk 0, fused LSTM pointwise with
// c-state in registers, h/h' written, then software grid barrier.
__global__ __launch_bounds__(256)
void lstm_persistent(const __nv_bfloat16* __restrict__ Whhp,
                     const float* __restrict__ Xp,
                     const float* __restrict__ c0,
                     float* __restrict__ hs,
                     __nv_bfloat16* __restrict__ hp)
{
    constexpr int BM = 64, BN = 128, WGN = 4;
    constexpr int WM = 32, WN = 32, MA = 2, NA = 4;
    constexpr int A_BYTES = BM * BK * 2;        // 4096
    constexpr int B_BYTES = BN * BK * 2;        // 8192
    constexpr int STG     = A_BYTES + B_BYTES;  // 12288
    constexpr int XP_OFF  = 4 * STG;            // 49152 (also > st region 33792)
    constexpr int BNP     = BN + 4;

    extern __shared__ __align__(128) char smem[];
    const uint32_t sb = smem_u32(smem);
    float* st   = reinterpret_cast<float*>(smem);            // [0, 33792) aliases stages 0-2
    float* xp_s = reinterpret_cast<float*>(smem + XP_OFF);   // [49152, 81920)

    const int tid = threadIdx.x;
    const int wid = tid >> 5;
    const int lid = tid & 31;
    const int wm  = wid / WGN;
    const int wn  = wid % WGN;
    const int bn0 = blockIdx.x * BN;
    const int bm0 = blockIdx.y * BM;
    const int j0  = bn0 >> 2;

    // c-state in registers: thread owns quads idx = tid + 256k (r=idx/32, jj=idx%32)
    float c_reg[8];
    #pragma unroll
    for (int k = 0; k < 8; ++k) {
        int idx = tid + 256 * k;
        int r = idx >> 5, jj = idx & 31;
        c_reg[k] = c0[(bm0 + r) * HID + j0 + jj];
    }

    unsigned bar_base = 0;
    if (tid == 0) bar_base = ld_acq(&g_bar_gen);

    for (int t = 0; t < SEQ; ++t) {
        const __nv_bfloat16* Ap = hp + (size_t)(t & 1) * BATCH * KP;
        __nv_bfloat16* hpn = hp + (size_t)((t + 1) & 1) * BATCH * KP;

        float acc[MA][NA][4];
        #pragma unroll
        for (int i = 0; i < MA; ++i)
            #pragma unroll
            for (int j = 0; j < NA; ++j)
                #pragma unroll
                for (int q = 0; q < 4; ++q) acc[i][j][q] = 0.f;

        auto load_chunk = [&](int c, int s) {
            const uint32_t ab = sb + s * STG;
            const uint32_t bb = ab + A_BYTES;
            const int k0 = c * BK;
            {   // A: 64 rows x 4 chunks = 256, one per thread
                int r = tid >> 2, cc = tid & 3;
                CP_ASYNC16(ab + swz(r, cc),
                           Ap + (size_t)(bm0 + r) * KP + k0 + cc * 8);
            }
            #pragma unroll
            for (int it = 0; it < 2; ++it) {
                int u = tid + it * 256;
                int r = u >> 2, cc = u & 3;
                CP_ASYNC16(bb + swz(r, cc),
                           Whhp + (size_t)(bn0 + r) * KP + k0 + cc * 8);
            }
        };

        // prologue: chunk 0 (+ Xp tile prefetch in same group), chunks 1, 2
        load_chunk(0, 0);
        {
            const float* xsrc = Xp + ((size_t)t * BATCH + bm0) * G4 + bn0;
            #pragma unroll
            for (int k = 0; k < 8; ++k) {
                int idx = tid + 256 * k;        // 2048 quads (64 rows x 32 quads)
                int r = idx >> 5, q = idx & 31;
                CP_ASYNC16(sb + XP_OFF + (uint32_t)idx * 16,
                           xsrc + (size_t)r * G4 + q * 4);
            }
        }
        CP_COMMIT();
        load_chunk(1, 1); CP_COMMIT();
        load_chunk(2, 2); CP_COMMIT();

        for (int c = 0; c < NC; ++c) {
            if (c <= NC - 3)      { CP_WAIT2(); }
            else if (c == NC - 2) { CP_WAIT1(); }
            else                  { CP_WAIT0(); }
            __syncthreads();
            if (c + 3 < NC) { load_chunk(c + 3, (c + 3) & 3); CP_COMMIT(); }

            const uint32_t ab = sb + (c & 3) * STG;
            const uint32_t bb = ab + A_BYTES;
            #pragma unroll
            for (int ks = 0; ks < 2; ++ks) {
                uint32_t afr[MA][4];
                #pragma unroll
                for (int ma = 0; ma < MA; ++ma) {
                    int row = wm * WM + ma * 16 + (lid & 15);
                    int cc  = 2 * ks + (lid >> 4);
                    LDMX4(afr[ma][0], afr[ma][1], afr[ma][2], afr[ma][3],
                          ab + swz(row, cc));
                }
                uint32_t bfr[NA][2];
                #pragma unroll
                for (int np = 0; np < NA / 2; ++np) {
                    int row = wn * WN + np * 16 + (lid & 15);
                    int cc  = 2 * ks + (lid >> 4);
                    uint32_t r0, r1, r2, r3;
                    LDMX4(r0, r1, r2, r3, bb + swz(row, cc));
                    bfr[2 * np + 0][0] = r0; bfr[2 * np + 1][0] = r1;
                    bfr[2 * np + 0][1] = r2; bfr[2 * np + 1][1] = r3;
                }
                #pragma unroll
                for (int ma = 0; ma < MA; ++ma)
                    #pragma unroll
                    for (int na = 0; na < NA; ++na)
                        MMA16816(acc[ma][na], afr[ma], bfr[na]);
            }
        }

        // stage accumulators to smem (region disjoint from stage 3 used by chunk 95)
        const int g  = lid >> 2;
        const int tg = lid & 3;
        #pragma unroll
        for (int ma = 0; ma < MA; ++ma) {
            #pragma unroll
            for (int na = 0; na < NA; ++na) {
                const int col = wn * WN + na * 8 + tg * 2;
                const int r0  = wm * WM + ma * 16 + g;
                const int r1  = r0 + 8;
                st[r0 * BNP + col]     = acc[ma][na][0];
                st[r0 * BNP + col + 1] = acc[ma][na][1];
                st[r1 * BNP + col]     = acc[ma][na][2];
                st[r1 * BNP + col + 1] = acc[ma][na][3];
            }
        }
        __syncthreads();

        // fused LSTM pointwise (gate-interleaved quads), c in registers
        float* hsrow = hs + (size_t)t * BH;
        #pragma unroll
        for (int k = 0; k < 8; ++k) {
            int idx = tid + 256 * k;
            int r = idx >> 5, jj = idx & 31;
            float4 gq = *reinterpret_cast<const float4*>(st + r * BNP + 4 * jj);
            float4 xq = *reinterpret_cast<const float4*>(xp_s + idx * 4);
            float gi = sigmf(gq.x + xq.x);
            float gf = sigmf(gq.y + xq.y);
            float gg = tanhf(gq.z + xq.z);
            float go = sigmf(gq.w + xq.w);
            float cv = gf * c_reg[k] + gi * gg;
            c_reg[k] = cv;
            float h = go * tanhf(cv);
            int b = bm0 + r;
            hsrow[b * HID + j0 + jj] = h;
            __nv_bfloat16 hi = __float2bfloat16(h);
            float lo = h - __bfloat162float(hi);
            size_t hb = (size_t)b * KP + j0 + jj;
            hpn[hb]        = hi;
            hpn[hb + 1024] = __float2bfloat16(lo);
            hpn[hb + 2048] = hi;
        }

        // software grid barrier (all 128 CTAs resident)
        __syncthreads();
        if (tid == 0) {
            __threadfence();
            unsigned a = atomicAdd(&g_bar_cnt, 1);
            if (a == 127u) {
                atomicExch(&g_bar_cnt, 0);
                __threadfence();
                atomicAdd(&g_bar_gen, 1);
            } else {
                unsigned target = bar_base + (unsigned)t + 1u;
                while ((int)(ld_acq(&g_bar_gen) - target) < 0) __nanosleep(64);
            }
        }
        __syncthreads();
    }
}

// ---------------- conversion kernels ---------------------------------------
// A-side split: [hi | lo | hi] ; B-side split: [hi | hi | lo]
__global__ void conv_A(const float* __restrict__ W, __nv_bfloat16* __restrict__ Wp, int total)
{
    int i = blockIdx.x * blockDim.x + threadIdx.x;
    if (i >= total) return;
    int r = i >> 10, k = i & 1023;
    float w = W[i];
    __nv_bfloat16 hi = __float2bfloat16(w);
    float lo = w - __bfloat162float(hi);
    size_t base = (size_t)r * KP;
    Wp[base + k]        = hi;
    Wp[base + 1024 + k] = __float2bfloat16(lo);
    Wp[base + 2048 + k] = hi;
}

__global__ void conv_B(const float* __restrict__ W, __nv_bfloat16* __restrict__ Wp, int total)
{
    int i = blockIdx.x * blockDim.x + threadIdx.x;
    if (i >= total) return;
    int r = i >> 10, k = i & 1023;
    float w = W[i];
    __nv_bfloat16 hi = __float2bfloat16(w);
    float lo = w - __bfloat162float(hi);
    size_t base = (size_t)r * KP;
    Wp[base + k]        = hi;
    Wp[base + 1024 + k] = hi;
    Wp[base + 2048 + k] = __float2bfloat16(lo);
}

// gate-interleaved row permutation: orig row q*1024+j -> j*4+q
__global__ void conv_B_perm(const float* __restrict__ W, __nv_bfloat16* __restrict__ Wp, int total)
{
    int i = blockIdx.x * blockDim.x + threadIdx.x;
    if (i >= total) return;
    int r = i >> 10, k = i & 1023;
    int q = r >> 10, j = r & 1023;
    float w = W[i];
    __nv_bfloat16 hi = __float2bfloat16(w);
    float lo = w - __bfloat162float(hi);
    size_t base = (size_t)(j * 4 + q) * KP;
    Wp[base + k]        = hi;
    Wp[base + 1024 + k] = hi;
    Wp[base + 2048 + k] = __float2bfloat16(lo);
}

__global__ void init_misc()
{
    if (threadIdx.x == 0 && blockIdx.x == 0) {
        g_bar_cnt = 0;
        g_bar_gen = 0;
    }
}

__global__ void bias_combine_perm(const float* __restrict__ b_ih, const float* __restrict__ b_hh)
{
    int i = blockIdx.x * blockDim.x + threadIdx.x;   // over G4
    if (i >= G4) return;
    int q = i >> 10, j = i & 1023;
    g_bias[j * 4 + q] = b_ih[i] + b_hh[i];
}

__global__ void softmax128(const float* __restrict__ W)
{
    int row = blockIdx.x;
    int t = threadIdx.x;
    int lane = t & 31, warp = t >> 5;
    __shared__ float red[4];
    float v = W[row * SEQ + t];

    float m = v;
    #pragma unroll
    for (int o = 16; o > 0; o >>= 1) m = fmaxf(m, __shfl_xor_sync(0xffffffffu, m, o));
    if (lane == 0) red[warp] = m;
    __syncthreads();
    m = fmaxf(fmaxf(red[0], red[1]), fmaxf(red[2], red[3]));
    __syncthreads();

    float e = expf(v - m);
    float s = e;
    #pragma unroll
    for (int o = 16; o > 0; o >>= 1) s += __shfl_xor_sync(0xffffffffu, s, o);
    if (lane == 0) red[warp] = s;
    __syncthreads();
    s = red[0] + red[1] + red[2] + red[3];
    g_A[row * SEQ + t] = e / s;
}

// att' (split-bf16 A-layout) = softmax(attnW) @ hs, written directly to g_Xbf
__global__ __launch_bounds__(128)
void attn_apply_fused()
{
    __shared__ float Asub[32][SEQ + 1];
    const int tid = threadIdx.x;
    const int n = blockIdx.x * 128 + tid;     // over BH (b*1024 + h)
    const int x0 = blockIdx.y * 32;

    for (int i = tid; i < 32 * SEQ; i += 128) {
        int xx = i >> 7;
        int y = i & 127;
        Asub[xx][y] = g_A[(x0 + xx) * SEQ + y];
    }
    __syncthreads();

    float acc[32];
    #pragma unroll
    for (int xx = 0; xx < 32; ++xx) acc[xx] = 0.f;

    for (int y = 0; y < SEQ; ++y) {
        float v = g_hs[(size_t)y * BH + n];
        #pragma unroll
        for (int xx = 0; xx < 32; ++xx)
            acc[xx] = fmaf(Asub[xx][y], v, acc[xx]);
    }

    const int b = n >> 10;
    const int h = n & 1023;
    #pragma unroll
    for (int xx = 0; xx < 32; ++xx) {
        float a = acc[xx];
        __nv_bfloat16 hi = __float2bfloat16(a);
        float lo = a - __bfloat162float(hi);
        size_t base = (size_t)((x0 + xx) * BATCH + b) * KP + h;
        g_Xbf[base]        = hi;
        g_Xbf[base + 1024] = __float2bfloat16(lo);
        g_Xbf[base + 2048] = hi;
    }
}

// ---------------- launch ----------------------------------------------------
extern "C" void kernel_launch(void* const* d_in, const int* in_sizes, int n_in,
                              void* d_out, int out_size)
{
    const float* inputs = (const float*)d_in[0];
    const float* h0     = (const float*)d_in[1];
    const float* c0     = (const float*)d_in[2];
    const float* W_ih   = (const float*)d_in[3];
    const float* W_hh   = (const float*)d_in[4];
    const float* b_ih   = (const float*)d_in[5];
    const float* b_hh   = (const float*)d_in[6];
    const float* attnW  = (const float*)d_in[7];
    const float* linW   = (const float*)d_in[8];
    const float* linb   = (const float*)d_in[9];
    float* out = (float*)d_out;

    void* p;
    cudaGetSymbolAddress(&p, g_Xp);    float* Xp    = (float*)p;
    cudaGetSymbolAddress(&p, g_hs);    float* hsb   = (float*)p;
    cudaGetSymbolAddress(&p, g_bias);  float* biasc = (float*)p;
    cudaGetSymbolAddress(&p, g_Xbf);   __nv_bfloat16* Xbf   = (__nv_bfloat16*)p;
    cudaGetSymbolAddress(&p, g_Wihp);  __nv_bfloat16* Wihp  = (__nv_bfloat16*)p;
    cudaGetSymbolAddress(&p, g_Whhp);  __nv_bfloat16* Whhp  = (__nv_bfloat16*)p;
    cudaGetSymbolAddress(&p, g_linWp); __nv_bfloat16* linWp = (__nv_bfloat16*)p;
    cudaGetSymbolAddress(&p, g_hp);    __nv_bfloat16* hp    = (__nv_bfloat16*)p;

    const int SMEM_BIG  = 2 * ((128 + 128) * BK * 2);   // 32768
    const int SMEM_PERS = 4 * ((64 + 128) * BK * 2) + 64 * 128 * 4;  // 49152 + 32768 = 81920

    cudaFuncSetAttribute((const void*)gemm_mma<128, 128, 2, 4>,
                         cudaFuncAttributeMaxDynamicSharedMemorySize, SMEM_BIG);
    cudaFuncSetAttribute((const void*)lstm_persistent,
                         cudaFuncAttributeMaxDynamicSharedMemorySize, SMEM_PERS);

    // launch order chosen so ncu (-s 5 -c 1) captures the Xp GEMM (index 5)
    conv_A<<<(SEQ * BATCH * 1024) / 256, 256>>>(inputs, Xbf, SEQ * BATCH * 1024);   // 0
    conv_B_perm<<<(G4 * 1024) / 256, 256>>>(W_ih, Wihp, G4 * 1024);                 // 1
    bias_combine_perm<<<(G4 + 255) / 256, 256>>>(b_ih, b_hh);                       // 2
    conv_B_perm<<<(G4 * 1024) / 256, 256>>>(W_hh, Whhp, G4 * 1024);                 // 3
    conv_A<<<(BATCH * 1024) / 256, 256>>>(h0, hp, BATCH * 1024);                    // 4

    // 5: Xp = X @ W_ih'^T + bias'
    gemm_mma<128, 128, 2, 4>
        <<<dim3(G4 / 128, (SEQ * BATCH) / 128), 256, SMEM_BIG>>>(
        Xbf, Wihp, biasc, Xp, G4, 1);

    init_misc<<<1, 32>>>();                                                          // 6
    softmax128<<<SEQ, SEQ>>>(attnW);                                                 // 7

    // 8: persistent recurrence (all 128 steps, c-state in registers)
    lstm_persistent<<<dim3(G4 / 128, BATCH / 64), 256, SMEM_PERS>>>(
        Whhp, Xp, c0, hsb, hp);

    // 9: attention mix, emitting split-bf16 att' directly into Xbf
    attn_apply_fused<<<dim3(BH / 128, SEQ / 32), 128>>>();

    conv_B<<<(OUTD * 1024) / 256, 256>>>(linW, linWp, OUTD * 1024);                  // 10

    // 11: out = att @ linW^T + linb
    gemm_mma<128, 128, 2, 4>
        <<<dim3(OUTD / 128, (SEQ * BATCH) / 128), 256, SMEM_BIG>>>(
        Xbf, linWp, linb, out, OUTD, 1);
}

// round 8
// speedup vs baseline: 2.3308x; 1.3813x over previous
#include <cuda_runtime.h>
#include <cuda_fp16.h>
#include <math.h>
#include <stdint.h>

// Problem dims
#define SEQ   128
#define BATCH 256
#define IND   1024
#define HID   1024
#define OUTD  1024
#define G4    4096
#define BH    (BATCH*HID)
#define KA    1024            // A' width (activations, fp16 rounded once)
#define KB    2048            // B' width (weights: [hi | lo] fp16 split)
#define BK    32
#define NC    (KB/BK)         // 64 k-chunks (A index wraps mod 32 chunks)

// ---------------- scratch (device globals) ---------------------------------
__device__ float g_Xp[(size_t)SEQ * BATCH * G4];     // 512 MB (gate-interleaved cols)
__device__ float g_hs[(size_t)SEQ * BATCH * HID];    // 128 MB
__device__ float g_A[SEQ * SEQ];
__device__ float g_bias[G4];                          // gate-interleaved
__device__ __half g_Xbf[(size_t)SEQ * BATCH * KA];    // 64 MB: X16 then att16
__device__ __half g_Wihp[(size_t)G4 * KB];            // 16 MB
__device__ __half g_Whhp[(size_t)G4 * KB];            // 16 MB
__device__ __half g_linWp[(size_t)OUTD * KB];         // 4 MB
__device__ __half g_hp[(size_t)2 * BATCH * KA];       // double-buffered h16
__device__ unsigned g_bar_cnt;
__device__ unsigned g_bar_gen;

// ---------------- PTX helpers ----------------------------------------------
__device__ __forceinline__ uint32_t smem_u32(const void* p) {
    uint32_t a;
    asm("{ .reg .u64 t; cvta.to.shared.u64 t, %1; cvt.u32.u64 %0, t; }"
        : "=r"(a) : "l"(p));
    return a;
}

#define CP_ASYNC16(dst, src) \
    asm volatile("cp.async.cg.shared.global [%0], [%1], 16;" :: "r"(dst), "l"(src))
#define CP_COMMIT()  asm volatile("cp.async.commit_group;" ::: "memory")
#define CP_WAIT2()   asm volatile("cp.async.wait_group 2;" ::: "memory")
#define CP_WAIT1()   asm volatile("cp.async.wait_group 1;" ::: "memory")
#define CP_WAIT0()   asm volatile("cp.async.wait_group 0;" ::: "memory")

#define LDMX4(r0, r1, r2, r3, addr) \
    asm volatile("ldmatrix.sync.aligned.m8n8.x4.shared.b16 {%0,%1,%2,%3}, [%4];" \
                 : "=r"(r0), "=r"(r1), "=r"(r2), "=r"(r3) : "r"(addr))

#define MMA16816(d, a, b) \
    asm volatile("mma.sync.aligned.m16n8k16.row.col.f32.f16.f16.f32 " \
                 "{%0,%1,%2,%3}, {%4,%5,%6,%7}, {%8,%9}, {%0,%1,%2,%3};" \
                 : "+f"((d)[0]), "+f"((d)[1]), "+f"((d)[2]), "+f"((d)[3]) \
                 : "r"((a)[0]), "r"((a)[1]), "r"((a)[2]), "r"((a)[3]), \
                   "r"((b)[0]), "r"((b)[1]))

// swizzled 16B-chunk byte offset within a tile (row has 4 chunks of 8 fp16)
__device__ __forceinline__ uint32_t swz(int row, int c) {
    return (uint32_t)((row * 4 + (c ^ ((row >> 1) & 3))) * 16);
}

__device__ __forceinline__ float sigmf(float x) {
    return 1.0f / (1.0f + __expf(-x));
}

__device__ __forceinline__ unsigned ld_acq(unsigned* p) {
    unsigned v;
    asm volatile("ld.acquire.gpu.global.u32 %0, [%1];" : "=r"(v) : "l"(p) : "memory");
    return v;
}

// ---------------- fp16 2-term HMMA GEMM (big GEMMs) -------------------------
// C[M,N] = A16[M,KA] @ B'[N,KB]^T (+bias), fp32 accum; A chunk index wraps
// mod KA so the computed product is ah * (bhi + blo) = ah * b_fp32.
// 256 threads = 8 warps (WGM x WGN). BK=32, 4-stage cp.async, 1 sync/chunk.
template<int BM, int BN, int WGM, int WGN>
__global__ __launch_bounds__(256)
void gemm_mma(const __half* __restrict__ A,
              const __half* __restrict__ B,
              const float* __restrict__ bias,
              float* __restrict__ C,
              int N, int hasBias)
{
    constexpr int WM = BM / WGM;
    constexpr int WN = BN / WGN;
    constexpr int MA = WM / 16;
    constexpr int NA = WN / 8;
    constexpr int A_BYTES = BM * BK * 2;
    constexpr int B_BYTES = BN * BK * 2;
    constexpr int STAGE   = A_BYTES + B_BYTES;

    extern __shared__ __align__(128) char smem[];
    const uint32_t sb = smem_u32(smem);

    const int tid = threadIdx.x;
    const int wid = tid >> 5;
    const int lid = tid & 31;
    const int g   = lid >> 2;
    const int tg  = lid & 3;
    const int wm  = wid / WGN;
    const int wn  = wid % WGN;
    const int bm0 = blockIdx.y * BM;
    const int bn0 = blockIdx.x * BN;

    float acc[MA][NA][4];
    #pragma unroll
    for (int i = 0; i < MA; ++i)
        #pragma unroll
        for (int j = 0; j < NA; ++j)
            #pragma unroll
            for (int q = 0; q < 4; ++q) acc[i][j][q] = 0.f;

    auto load_tile = [&](int c, int s) {
        const uint32_t abase = sb + s * STAGE;
        const uint32_t bbase = abase + A_BYTES;
        const int ka0 = (c & (KA / BK - 1)) * BK;   // A wraps
        const int kb0 = c * BK;
        #pragma unroll
        for (int u = tid; u < BM * 4; u += 256) {
            int r = u >> 2, cc = u & 3;
            CP_ASYNC16(abase + swz(r, cc),
                       A + (size_t)(bm0 + r) * KA + ka0 + cc * 8);
        }
        #pragma unroll
        for (int u = tid; u < BN * 4; u += 256) {
            int r = u >> 2, cc = u & 3;
            CP_ASYNC16(bbase + swz(r, cc),
                       B + (size_t)(bn0 + r) * KB + kb0 + cc * 8);
        }
    };

    load_tile(0, 0); CP_COMMIT();
    load_tile(1, 1); CP_COMMIT();
    load_tile(2, 2); CP_COMMIT();

    for (int c = 0; c < NC; ++c) {
        if (c <= NC - 3)      { CP_WAIT2(); }
        else if (c == NC - 2) { CP_WAIT1(); }
        else                  { CP_WAIT0(); }
        __syncthreads();
        if (c + 3 < NC) { load_tile(c + 3, (c + 3) & 3); CP_COMMIT(); }

        const uint32_t abase = sb + (c & 3) * STAGE;
        const uint32_t bbase = abase + A_BYTES;

        #pragma unroll
        for (int ks = 0; ks < 2; ++ks) {
            uint32_t afr[MA][4];
            #pragma unroll
            for (int ma = 0; ma < MA; ++ma) {
                int row = wm * WM + ma * 16 + (lid & 15);
                int cc  = 2 * ks + (lid >> 4);
                LDMX4(afr[ma][0], afr[ma][1], afr[ma][2], afr[ma][3],
                      abase + swz(row, cc));
            }
            uint32_t bfr[NA][2];
            #pragma unroll
            for (int np = 0; np < NA / 2; ++np) {
                int row = wn * WN + np * 16 + (lid & 15);
                int cc  = 2 * ks + (lid >> 4);
                uint32_t r0, r1, r2, r3;
                LDMX4(r0, r1, r2, r3, bbase + swz(row, cc));
                bfr[2 * np + 0][0] = r0; bfr[2 * np + 1][0] = r1;
                bfr[2 * np + 0][1] = r2; bfr[2 * np + 1][1] = r3;
            }
            #pragma unroll
            for (int ma = 0; ma < MA; ++ma)
                #pragma unroll
                for (int na = 0; na < NA; ++na)
                    MMA16816(acc[ma][na], afr[ma], bfr[na]);
        }
    }

    #pragma unroll
    for (int ma = 0; ma < MA; ++ma) {
        #pragma unroll
        for (int na = 0; na < NA; ++na) {
            const int col = bn0 + wn * WN + na * 8 + tg * 2;
            const int r0  = bm0 + wm * WM + ma * 16 + g;
            const int r1  = r0 + 8;
            float2 v0 = make_float2(acc[ma][na][0], acc[ma][na][1]);
            float2 v1 = make_float2(acc[ma][na][2], acc[ma][na][3]);
            if (hasBias) {
                float2 bv = *reinterpret_cast<const float2*>(bias + col);
                v0.x += bv.x; v0.y += bv.y; v1.x += bv.x; v1.y += bv.y;
            }
            *reinterpret_cast<float2*>(C + (size_t)r0 * N + col) = v0;
            *reinterpret_cast<float2*>(C + (size_t)r1 * N + col) = v1;
        }
    }
}

// ---------------- persistent LSTM recurrence --------------------------------
// 128 CTAs (grid 32x4), all resident. Per step: 64x128 tile of
// gates = h16 @ W_hh'^T (KB=2048, A wraps mod 1024), Xp[t] tile prefetched,
// fused pointwise with c-state in registers, then software grid barrier.
__global__ __launch_bounds__(256)
void lstm_persistent(const __half* __restrict__ Whhp,
                     const float* __restrict__ Xp,
                     const float* __restrict__ c0,
                     float* __restrict__ hs,
                     __half* __restrict__ hp)
{
    constexpr int BM = 64, BN = 128, WGN = 4;
    constexpr int WM = 32, WN = 32, MA = 2, NA = 4;
    constexpr int A_BYTES = BM * BK * 2;        // 4096
    constexpr int B_BYTES = BN * BK * 2;        // 8192
    constexpr int STG     = A_BYTES + B_BYTES;  // 12288
    constexpr int XP_OFF  = 4 * STG;            // 49152 (also > st region 33792)
    constexpr int BNP     = BN + 4;

    extern __shared__ __align__(128) char smem[];
    const uint32_t sb = smem_u32(smem);
    float* st   = reinterpret_cast<float*>(smem);            // [0, 33792)
    float* xp_s = reinterpret_cast<float*>(smem + XP_OFF);   // [49152, 81920)

    const int tid = threadIdx.x;
    const int wid = tid >> 5;
    const int lid = tid & 31;
    const int wm  = wid / WGN;
    const int wn  = wid % WGN;
    const int bn0 = blockIdx.x * BN;
    const int bm0 = blockIdx.y * BM;
    const int j0  = bn0 >> 2;

    float c_reg[8];
    #pragma unroll
    for (int k = 0; k < 8; ++k) {
        int idx = tid + 256 * k;
        int r = idx >> 5, jj = idx & 31;
        c_reg[k] = c0[(bm0 + r) * HID + j0 + jj];
    }

    unsigned bar_base = 0;
    if (tid == 0) bar_base = ld_acq(&g_bar_gen);

    for (int t = 0; t < SEQ; ++t) {
        const __half* Ap = hp + (size_t)(t & 1) * BATCH * KA;
        __half* hpn = hp + (size_t)((t + 1) & 1) * BATCH * KA;

        float acc[MA][NA][4];
        #pragma unroll
        for (int i = 0; i < MA; ++i)
            #pragma unroll
            for (int j = 0; j < NA; ++j)
                #pragma unroll
                for (int q = 0; q < 4; ++q) acc[i][j][q] = 0.f;

        auto load_chunk = [&](int c, int s) {
            const uint32_t ab = sb + s * STG;
            const uint32_t bb = ab + A_BYTES;
            const int ka0 = (c & (KA / BK - 1)) * BK;
            const int kb0 = c * BK;
            {   // A: 64 rows x 4 chunks = 256, one per thread
                int r = tid >> 2, cc = tid & 3;
                CP_ASYNC16(ab + swz(r, cc),
                           Ap + (size_t)(bm0 + r) * KA + ka0 + cc * 8);
            }
            #pragma unroll
            for (int it = 0; it < 2; ++it) {
                int u = tid + it * 256;
                int r = u >> 2, cc = u & 3;
                CP_ASYNC16(bb + swz(r, cc),
                           Whhp + (size_t)(bn0 + r) * KB + kb0 + cc * 8);
            }
        };

        load_chunk(0, 0);
        {
            const float* xsrc = Xp + ((size_t)t * BATCH + bm0) * G4 + bn0;
            #pragma unroll
            for (int k = 0; k < 8; ++k) {
                int idx = tid + 256 * k;        // 2048 quads (64 rows x 32 quads)
                int r = idx >> 5, q = idx & 31;
                CP_ASYNC16(sb + XP_OFF + (uint32_t)idx * 16,
                           xsrc + (size_t)r * G4 + q * 4);
            }
        }
        CP_COMMIT();
        load_chunk(1, 1); CP_COMMIT();
        load_chunk(2, 2); CP_COMMIT();

        for (int c = 0; c < NC; ++c) {
            if (c <= NC - 3)      { CP_WAIT2(); }
            else if (c == NC - 2) { CP_WAIT1(); }
            else                  { CP_WAIT0(); }
            __syncthreads();
            if (c + 3 < NC) { load_chunk(c + 3, (c + 3) & 3); CP_COMMIT(); }

            const uint32_t ab = sb + (c & 3) * STG;
            const uint32_t bb = ab + A_BYTES;
            #pragma unroll
            for (int ks = 0; ks < 2; ++ks) {
                uint32_t afr[MA][4];
                #pragma unroll
                for (int ma = 0; ma < MA; ++ma) {
                    int row = wm * WM + ma * 16 + (lid & 15);
                    int cc  = 2 * ks + (lid >> 4);
                    LDMX4(afr[ma][0], afr[ma][1], afr[ma][2], afr[ma][3],
                          ab + swz(row, cc));
                }
                uint32_t bfr[NA][2];
                #pragma unroll
                for (int np = 0; np < NA / 2; ++np) {
                    int row = wn * WN + np * 16 + (lid & 15);
                    int cc  = 2 * ks + (lid >> 4);
                    uint32_t r0, r1, r2, r3;
                    LDMX4(r0, r1, r2, r3, bb + swz(row, cc));
                    bfr[2 * np + 0][0] = r0; bfr[2 * np + 1][0] = r1;
                    bfr[2 * np + 0][1] = r2; bfr[2 * np + 1][1] = r3;
                }
                #pragma unroll
                for (int ma = 0; ma < MA; ++ma)
                    #pragma unroll
                    for (int na = 0; na < NA; ++na)
                        MMA16816(acc[ma][na], afr[ma], bfr[na]);
            }
        }

        const int g  = lid >> 2;
        const int tg = lid & 3;
        #pragma unroll
        for (int ma = 0; ma < MA; ++ma) {
            #pragma unroll
            for (int na = 0; na < NA; ++na) {
                const int col = wn * WN + na * 8 + tg * 2;
                const int r0  = wm * WM + ma * 16 + g;
                const int r1  = r0 + 8;
                st[r0 * BNP + col]     = acc[ma][na][0];
                st[r0 * BNP + col + 1] = acc[ma][na][1];
                st[r1 * BNP + col]     = acc[ma][na][2];
                st[r1 * BNP + col + 1] = acc[ma][na][3];
            }
        }
        __syncthreads();

        float* hsrow = hs + (size_t)t * BH;
        #pragma unroll
        for (int k = 0; k < 8; ++k) {
            int idx = tid + 256 * k;
            int r = idx >> 5, jj = idx & 31;
            float4 gq = *reinterpret_cast<const float4*>(st + r * BNP + 4 * jj);
            float4 xq = *reinterpret_cast<const float4*>(xp_s + idx * 4);
            float gi = sigmf(gq.x + xq.x);
            float gf = sigmf(gq.y + xq.y);
            float gg = tanhf(gq.z + xq.z);
            float go = sigmf(gq.w + xq.w);
            float cv = gf * c_reg[k] + gi * gg;
            c_reg[k] = cv;
            float h = go * tanhf(cv);
            int b = bm0 + r;
            hsrow[b * HID + j0 + jj] = h;
            hpn[(size_t)b * KA + j0 + jj] = __float2half(h);
        }

        __syncthreads();
        if (tid == 0) {
            __threadfence();
            unsigned a = atomicAdd(&g_bar_cnt, 1);
            if (a == 127u) {
                atomicExch(&g_bar_cnt, 0);
                __threadfence();
                atomicAdd(&g_bar_gen, 1);
            } else {
                unsigned target = bar_base + (unsigned)t + 1u;
                while ((int)(ld_acq(&g_bar_gen) - target) < 0) __nanosleep(64);
            }
        }
        __syncthreads();
    }
}

// ---------------- conversion kernels ---------------------------------------
// Activations: plain fp16 cast. Weights: [hi | lo] fp16 split (exact pair).
__global__ void conv_act(const float* __restrict__ W, __half* __restrict__ Wp, int total)
{
    int i = blockIdx.x * blockDim.x + threadIdx.x;
    if (i >= total) return;
    Wp[i] = __float2half(W[i]);
}

__global__ void conv_wt(const float* __restrict__ W, __half* __restrict__ Wp, int total)
{
    int i = blockIdx.x * blockDim.x + threadIdx.x;
    if (i >= total) return;
    int r = i >> 10, k = i & 1023;
    float w = W[i];
    __half hi = __float2half(w);
    float lo = w - __half2float(hi);
    size_t base = (size_t)r * KB;
    Wp[base + k]        = hi;
    Wp[base + 1024 + k] = __float2half(lo);
}

// gate-interleaved row permutation: orig row q*1024+j -> j*4+q
__global__ void conv_wt_perm(const float* __restrict__ W, __half* __restrict__ Wp, int total)
{
    int i = blockIdx.x * blockDim.x + threadIdx.x;
    if (i >= total) return;
    int r = i >> 10, k = i & 1023;
    int q = r >> 10, j = r & 1023;
    float w = W[i];
    __half hi = __float2half(w);
    float lo = w - __half2float(hi);
    size_t base = (size_t)(j * 4 + q) * KB;
    Wp[base + k]        = hi;
    Wp[base + 1024 + k] = __float2half(lo);
}

__global__ void init_misc()
{
    if (threadIdx.x == 0 && blockIdx.x == 0) {
        g_bar_cnt = 0;
        g_bar_gen = 0;
    }
}

__global__ void bias_combine_perm(const float* __restrict__ b_ih, const float* __restrict__ b_hh)
{
    int i = blockIdx.x * blockDim.x + threadIdx.x;   // over G4
    if (i >= G4) return;
    int q = i >> 10, j = i & 1023;
    g_bias[j * 4 + q] = b_ih[i] + b_hh[i];
}

__global__ void softmax128(const float* __restrict__ W)
{
    int row = blockIdx.x;
    int t = threadIdx.x;
    int lane = t & 31, warp = t >> 5;
    __shared__ float red[4];
    float v = W[row * SEQ + t];

    float m = v;
    #pragma unroll
    for (int o = 16; o > 0; o >>= 1) m = fmaxf(m, __shfl_xor_sync(0xffffffffu, m, o));
    if (lane == 0) red[warp] = m;
    __syncthreads();
    m = fmaxf(fmaxf(red[0], red[1]), fmaxf(red[2], red[3]));
    __syncthreads();

    float e = expf(v - m);
    float s = e;
    #pragma unroll
    for (int o = 16; o > 0; o >>= 1) s += __shfl_xor_sync(0xffffffffu, s, o);
    if (lane == 0) red[warp] = s;
    __syncthreads();
    s = red[0] + red[1] + red[2] + red[3];
    g_A[row * SEQ + t] = e / s;
}

// att16 = fp16(softmax(attnW) @ hs), written directly into g_Xbf
__global__ __launch_bounds__(128)
void attn_apply_fused()
{
    __shared__ float Asub[32][SEQ + 1];
    const int tid = threadIdx.x;
    const int n = blockIdx.x * 128 + tid;     // over BH (b*1024 + h)
    const int x0 = blockIdx.y * 32;

    for (int i = tid; i < 32 * SEQ; i += 128) {
        int xx = i >> 7;
        int y = i & 127;
        Asub[xx][y] = g_A[(x0 + xx) * SEQ + y];
    }
    __syncthreads();

    float acc[32];
    #pragma unroll
    for (int xx = 0; xx < 32; ++xx) acc[xx] = 0.f;

    for (int y = 0; y < SEQ; ++y) {
        float v = g_hs[(size_t)y * BH + n];
        #pragma unroll
        for (int xx = 0; xx < 32; ++xx)
            acc[xx] = fmaf(Asub[xx][y], v, acc[xx]);
    }

    const int b = n >> 10;
    const int h = n & 1023;
    #pragma unroll
    for (int xx = 0; xx < 32; ++xx)
        g_Xbf[(size_t)((x0 + xx) * BATCH + b) * KA + h] = __float2half(acc[xx]);
}

// ---------------- launch ----------------------------------------------------
extern "C" void kernel_launch(void* const* d_in, const int* in_sizes, int n_in,
                              void* d_out, int out_size)
{
    const float* inputs = (const float*)d_in[0];
    const float* h0     = (const float*)d_in[1];
    const float* c0     = (const float*)d_in[2];
    const float* W_ih   = (const float*)d_in[3];
    const float* W_hh   = (const float*)d_in[4];
    const float* b_ih   = (const float*)d_in[5];
    const float* b_hh   = (const float*)d_in[6];
    const float* attnW  = (const float*)d_in[7];
    const float* linW   = (const float*)d_in[8];
    const float* linb   = (const float*)d_in[9];
    float* out = (float*)d_out;

    void* p;
    cudaGetSymbolAddress(&p, g_Xp);    float* Xp    = (float*)p;
    cudaGetSymbolAddress(&p, g_hs);    float* hsb   = (float*)p;
    cudaGetSymbolAddress(&p, g_bias);  float* biasc = (float*)p;
    cudaGetSymbolAddress(&p, g_Xbf);   __half* Xbf   = (__half*)p;
    cudaGetSymbolAddress(&p, g_Wihp);  __half* Wihp  = (__half*)p;
    cudaGetSymbolAddress(&p, g_Whhp);  __half* Whhp  = (__half*)p;
    cudaGetSymbolAddress(&p, g_linWp); __half* linWp = (__half*)p;
    cudaGetSymbolAddress(&p, g_hp);    __half* hp    = (__half*)p;

    const int SMEM_BIG  = 4 * ((128 + 128) * BK * 2);                 // 65536
    const int SMEM_PERS = 4 * ((64 + 128) * BK * 2) + 64 * 128 * 4;   // 81920

    cudaFuncSetAttribute((const void*)gemm_mma<128, 128, 2, 4>,
                         cudaFuncAttributeMaxDynamicSharedMemorySize, SMEM_BIG);
    cudaFuncSetAttribute((const void*)lstm_persistent,
                         cudaFuncAttributeMaxDynamicSharedMemorySize, SMEM_PERS);

    conv_act<<<(SEQ * BATCH * 1024) / 256, 256>>>(inputs, Xbf, SEQ * BATCH * 1024); // 0
    conv_wt_perm<<<(G4 * 1024) / 256, 256>>>(W_ih, Wihp, G4 * 1024);                // 1
    bias_combine_perm<<<(G4 + 255) / 256, 256>>>(b_ih, b_hh);                       // 2
    conv_wt_perm<<<(G4 * 1024) / 256, 256>>>(W_hh, Whhp, G4 * 1024);                // 3
    conv_act<<<(BATCH * 1024) / 256, 256>>>(h0, hp, BATCH * 1024);                  // 4

    // 5: Xp = X16 @ W_ih'^T + bias'
    gemm_mma<128, 128, 2, 4>
        <<<dim3(G4 / 128, (SEQ * BATCH) / 128), 256, SMEM_BIG>>>(
        Xbf, Wihp, biasc, Xp, G4, 1);

    init_misc<<<1, 32>>>();                                                          // 6
    softmax128<<<SEQ, SEQ>>>(attnW);                                                 // 7

    // 8: persistent recurrence (all 128 steps, c-state in registers)
    lstm_persistent<<<dim3(G4 / 128, BATCH / 64), 256, SMEM_PERS>>>(
        Whhp, Xp, c0, hsb, hp);

    // 9: attention mix -> fp16 att directly into Xbf
    attn_apply_fused<<<dim3(BH / 128, SEQ / 32), 128>>>();

    conv_wt<<<(OUTD * 1024) / 256, 256>>>(linW, linWp, OUTD * 1024);                 // 10

    // 11: out = att16 @ linW'^T + linb
    gemm_mma<128, 128, 2, 4>
        <<<dim3(OUTD / 128, (SEQ * BATCH) / 128), 256, SMEM_BIG>>>(
        Xbf, linWp, linb, out, OUTD, 1);
}